// round 9
// baseline (speedup 1.0000x reference)
#include <cuda_runtime.h>
#include <cmath>

// ---------------------------------------------------------------------------
// CTLNN persistent kernel, round 9.
// R8 layout (128 CTAs = 2 row-halves x 64 col-groups; 32 rows x 8 cols per
// CTA; threads (r:32, ch:2, kp:8), 4 cols per thread over a K/8 slice) plus:
//  - distributed grid barrier: 16 padded counters, 8 CTAs each (kills the
//    128-deep same-address atomic serialization, ~3.5k cyc/barrier)
//  - LN reduction: ch-halves combined in SMEM, one (s,q) atomic pair per
//    (CTA,row) instead of two
// LayerNorm folded into phase A; cp.async double-buffered staging; FFMA2.
// ---------------------------------------------------------------------------

namespace {
constexpr int Tt   = 1024;
constexpr int DIN  = 256;
constexpr int Hh   = 512;
constexpr int NCTA = 128;
constexpr int NTHR = 512;
constexpr int NBAR = 16;            // distributed barrier counters
constexpr int BARSTRIDE = 32;       // 128B apart
constexpr float DTc  = 0.01f;
constexpr float EPSc = 1e-5f;

// SMEM float offsets
constexpr int OFF_WMX   = 0;        // 16 x 256 (x-rows of Wm) [c16][k]
constexpr int OFF_WMV   = 4096;     // 16 x 512 (h-rows, gamma-folded)
constexpr int OFF_WT    = 12288;    // 8 x 512
constexpr int OFF_WF1   = 16384;
constexpr int OFF_WF2   = 20480;
constexpr int OFF_STAGE = 24576;    // 2 buffers x (32 rows x 64 granules) f4
constexpr int OFF_RED   = 40960;    // 512 x 8 floats
constexpr int OFF_LNR   = OFF_RED + 2048;  // 128 floats (phase-D tail reuse)
constexpr int OFF_B     = 45056;    // 88 consts
constexpr int OFF_RSTD  = 45144;    // 32
constexpr int SMEM_FLOATS = 45184;  // ~180.7 KB
// OFF_B: 0 bmg[8] 8 bmc[8] 16 bt[8] 24 bf1[8] 32 bf2[8] 40 gam[8] 48 bet[8]
//        56 Bsum[16] (g0..7,core0..7)  72 Gsum[16]
}

// Cross-CTA state
__device__ unsigned g_barArr[NBAR * BARSTRIDE];
__device__ float g_rs[128], g_rq[128];     // [par][globalRow]
__device__ float g_v[64 * Hh];
__device__ float g_core[64 * Hh];
__device__ float g_z[64 * Hh];
__device__ float g_a1[64 * Hh];

__global__ void ctlnn_reset() {
    int i = blockIdx.x * blockDim.x + threadIdx.x;
    if (i < NBAR * BARSTRIDE) g_barArr[i] = 0u;
    if (i < 128) { g_rs[i] = 0.f; g_rq[i] = 0.f; }
    for (int k = i; k < 64 * Hh; k += gridDim.x * blockDim.x) g_v[k] = 0.f;
}

// ---- helpers --------------------------------------------------------------
__device__ __forceinline__ void cp16(float4* dst, const void* src) {
    unsigned s = (unsigned)__cvta_generic_to_shared(dst);
    asm volatile("cp.async.cg.shared.global [%0], [%1], 16;" :: "r"(s), "l"(src));
}
__device__ __forceinline__ void cp_commit() {
    asm volatile("cp.async.commit_group;" ::: "memory");
}
template <int N>
__device__ __forceinline__ void cp_wait() {
    asm volatile("cp.async.wait_group %0;" :: "n"(N) : "memory");
}
__device__ __forceinline__ void fma2(unsigned long long& d,
                                     unsigned long long a, unsigned long long b) {
    asm volatile("fma.rn.f32x2 %0, %1, %2, %3;" : "=l"(d) : "l"(a), "l"(b), "l"(d));
}
__device__ __forceinline__ unsigned long long mul2(unsigned long long a,
                                                   unsigned long long b) {
    unsigned long long d;
    asm("mul.rn.f32x2 %0, %1, %2;" : "=l"(d) : "l"(a), "l"(b));
    return d;
}
__device__ __forceinline__ float hsum(unsigned long long u) {
    float lo, hi;
    asm("mov.b64 {%0,%1}, %2;" : "=f"(lo), "=f"(hi) : "l"(u));
    return lo + hi;
}

// Distributed grid barrier: CTA bid arrives on counter (bid % 16); 8 CTAs per
// counter. Waiters: threads 0..15 each poll one counter to target8.
__device__ __forceinline__ void grid_bar(unsigned target8) {
    __threadfence();
    __syncthreads();
    if (threadIdx.x == 0)
        atomicAdd(&g_barArr[(blockIdx.x & (NBAR - 1)) * BARSTRIDE], 1u);
    if (threadIdx.x < NBAR) {
        unsigned v;
        do {
            asm volatile("ld.global.acquire.gpu.u32 %0, [%1];"
                         : "=r"(v) : "l"(&g_barArr[threadIdx.x * BARSTRIDE]));
        } while (v < target8);
    }
    __syncthreads();
}

// Stage one 32-row x 64-granule(16B) chunk into SMEM with XOR swizzle.
__device__ __forceinline__ void stage32(float4* __restrict__ dst,
                                        const char* __restrict__ gbase,
                                        size_t rstrideB, int rs0, int kk) {
#pragma unroll
    for (int i = 0; i < 4; ++i) {
        int rs = rs0 + i * 8;
        cp16(dst + rs * 64 + (kk ^ (rs & 7)),
             gbase + (size_t)rs * rstrideB + kk * 16);
    }
    cp_commit();
}

// Phase-A x-dot: 8 outputs (4 g + 4 core), weight col stride 64 granules.
__device__ __forceinline__ void dotAx(const ulonglong2* __restrict__ sp, int sw,
                                      int kp,
                                      const ulonglong2* __restrict__ wg,
                                      const ulonglong2* __restrict__ wc,
                                      unsigned long long ag[4][2],
                                      unsigned long long ac[4][2]) {
#pragma unroll
    for (int j = 0; j < 8; ++j) {
        int l = j * 8 + kp;
        ulonglong2 a = sp[l ^ sw];
#pragma unroll
        for (int cc = 0; cc < 4; ++cc) {
            ulonglong2 g = wg[cc * 64 + l];
            ulonglong2 c = wc[cc * 64 + l];
            fma2(ag[cc][0], a.x, g.x); fma2(ag[cc][1], a.y, g.y);
            fma2(ac[cc][0], a.x, c.x); fma2(ac[cc][1], a.y, c.y);
        }
    }
}
// Phase-A v-dot (rstd-scaled), weight col stride 128 granules.
__device__ __forceinline__ void dotAv(const ulonglong2* __restrict__ sp, int sw,
                                      int kp, int goff,
                                      unsigned long long rstd2,
                                      const ulonglong2* __restrict__ wg,
                                      const ulonglong2* __restrict__ wc,
                                      unsigned long long ag[4][2],
                                      unsigned long long ac[4][2]) {
#pragma unroll
    for (int j = 0; j < 8; ++j) {
        int l = j * 8 + kp;
        ulonglong2 a = sp[l ^ sw];
        a.x = mul2(a.x, rstd2); a.y = mul2(a.y, rstd2);
        int wi = goff + l;
#pragma unroll
        for (int cc = 0; cc < 4; ++cc) {
            ulonglong2 g = wg[cc * 128 + wi];
            ulonglong2 c = wc[cc * 128 + wi];
            fma2(ag[cc][0], a.x, g.x); fma2(ag[cc][1], a.y, g.y);
            fma2(ac[cc][0], a.x, c.x); fma2(ac[cc][1], a.y, c.y);
        }
    }
}
// Generic 4-col dot (phases B/C/D), weight col stride 128 granules.
__device__ __forceinline__ void dot4(const ulonglong2* __restrict__ sp, int sw,
                                     int kp, int goff,
                                     const ulonglong2* __restrict__ w,
                                     unsigned long long acc[4][2]) {
#pragma unroll
    for (int j = 0; j < 8; ++j) {
        int l = j * 8 + kp;
        ulonglong2 a = sp[l ^ sw];
        int wi = goff + l;
#pragma unroll
        for (int cc = 0; cc < 4; ++cc) {
            ulonglong2 ww = w[cc * 128 + wi];
            fma2(acc[cc][0], a.x, ww.x);
            fma2(acc[cc][1], a.y, ww.y);
        }
    }
}

__global__ void __launch_bounds__(NTHR, 1)
ctlnn_main(const float* __restrict__ x,
           const float* __restrict__ Wm,  const float* __restrict__ bm,
           const float* __restrict__ Wf1, const float* __restrict__ bf1,
           const float* __restrict__ Wf2, const float* __restrict__ bf2,
           const float* __restrict__ Wt,  const float* __restrict__ bt,
           const float* __restrict__ gamma, const float* __restrict__ beta,
           float* __restrict__ out) {
    extern __shared__ __align__(16) float sm[];
    const int tid = threadIdx.x;
    const int bid = blockIdx.x;
    const int rh  = bid >> 6;        // row half
    const int cg  = bid & 63;        // column group
    const int cbase = cg * 8;        // first owned H-column

    // ---- one-time weight slice load ----
    for (int idx = tid; idx < 16 * 256; idx += NTHR) {   // Wm x-rows
        int c = idx >> 8, k = idx & 255;
        int srccol = (c < 8) ? (cbase + c) : (512 + cbase + (c - 8));
        sm[OFF_WMX + idx] = Wm[k * 1024 + srccol];
    }
    for (int idx = tid; idx < 16 * 512; idx += NTHR) {   // Wm h-rows * gamma
        int c = idx >> 9, k = idx & 511;
        int srccol = (c < 8) ? (cbase + c) : (512 + cbase + (c - 8));
        sm[OFF_WMV + idx] = Wm[(256 + k) * 1024 + srccol] * gamma[k];
    }
    for (int idx = tid; idx < 8 * 512; idx += NTHR) {
        int c = idx >> 9, k = idx & 511;
        int col = cbase + c;
        sm[OFF_WT  + idx] = Wt [k * 512 + col];
        sm[OFF_WF1 + idx] = Wf1[k * 512 + col];
        sm[OFF_WF2 + idx] = Wf2[k * 512 + col];
    }
    if (tid < 8) {
        int col = cbase + tid;
        sm[OFF_B +  0 + tid] = bm[col];
        sm[OFF_B +  8 + tid] = bm[512 + col];
        sm[OFF_B + 16 + tid] = bt[col];
        sm[OFF_B + 24 + tid] = bf1[col];
        sm[OFF_B + 32 + tid] = bf2[col];
        sm[OFF_B + 40 + tid] = gamma[col];
        sm[OFF_B + 48 + tid] = beta[col];
    }
    {   // per-column LN-fold constants Bsum/Gsum (16 A-cols)
        int w = tid >> 5, lane = tid & 31;
        if (w < 16) {
            int srccol = (w < 8) ? (cbase + w) : (512 + cbase + (w - 8));
            float sb = 0.f, sg = 0.f;
            for (int k = lane; k < 512; k += 32) {
                float wv = Wm[(256 + k) * 1024 + srccol];
                sb += beta[k] * wv;
                sg += gamma[k] * wv;
            }
#pragma unroll
            for (int o = 16; o; o >>= 1) {
                sb += __shfl_xor_sync(~0u, sb, o);
                sg += __shfl_xor_sync(~0u, sg, o);
            }
            if (lane == 0) { sm[OFF_B + 56 + w] = sb; sm[OFF_B + 72 + w] = sg; }
        }
    }
    __syncthreads();

    float4* bufA = reinterpret_cast<float4*>(sm + OFF_STAGE);
    float4* bufB = bufA + 32 * 64;
    float4* red4 = reinterpret_cast<float4*>(sm + OFF_RED);

    const int r   = tid & 31;         // local row
    const int ch  = (tid >> 5) & 1;   // column half
    const int kp  = tid >> 6;         // K-eighth
    const int sw  = r & 7;
    const int rs0 = tid >> 6;         // staging row phase
    const int kk  = tid & 63;         // staging granule
    const int gR  = rh * 32 + r;      // global batch row
    const int colw = ch * 4;          // first weight col within CTA
    const bool owner = (kp == 0);

    const ulonglong2* WMXg = reinterpret_cast<const ulonglong2*>(sm + OFF_WMX) + colw * 64;
    const ulonglong2* WMXc = reinterpret_cast<const ulonglong2*>(sm + OFF_WMX) + (8 + colw) * 64;
    const ulonglong2* WMVg = reinterpret_cast<const ulonglong2*>(sm + OFF_WMV) + colw * 128;
    const ulonglong2* WMVc = reinterpret_cast<const ulonglong2*>(sm + OFF_WMV) + (8 + colw) * 128;
    const ulonglong2* WTu  = reinterpret_cast<const ulonglong2*>(sm + OFF_WT)  + colw * 128;
    const ulonglong2* WF1u = reinterpret_cast<const ulonglong2*>(sm + OFF_WF1) + colw * 128;
    const ulonglong2* WF2u = reinterpret_cast<const ulonglong2*>(sm + OFF_WF2) + colw * 128;

    const char* xbase    = (const char*)(x + (size_t)rh * 32 * Tt * DIN);
    const char* vbase    = (const char*)(g_v    + (size_t)rh * 32 * Hh);
    const char* corebase = (const char*)(g_core + (size_t)rh * 32 * Hh);
    const char* zbase    = (const char*)(g_z    + (size_t)rh * 32 * Hh);
    const char* abase    = (const char*)(g_a1   + (size_t)rh * 32 * Hh);

    float hprev[4] = {0.f, 0.f, 0.f, 0.f};
    float dtT[4]   = {0.f, 0.f, 0.f, 0.f};
    float vkeep[4] = {0.f, 0.f, 0.f, 0.f};
    unsigned bar_t = 0;        // per-counter targets: +8 per barrier

    // prefetch x(t=0) into bufA (1 group pending at loop entry)
    stage32(bufA, xbase, (size_t)Tt * DIN * 4, rs0, kk);

    for (int t = 0; t < Tt; ++t) {
        const int par = t & 1;

        // ============ PHASE A: mapped = [x_t, h] @ Wm (LN folded) ==========
        stage32(bufB, vbase, Hh * 4, rs0, kk);              // v0 -> B
        float muv = 0.f, rstdv = 0.f;
        if (owner) {
            if (t > 0) {   // finalize step t-1: LN of vkeep, write out
                int pp = (t - 1) & 1;
                float s = __ldcg(&g_rs[pp * 64 + gR]);
                float q = __ldcg(&g_rq[pp * 64 + gR]);
                muv = s * (1.f / 512.f);
                float var = q * (1.f / 512.f) - muv * muv;
                rstdv = rsqrtf(var + EPSc);
                float4 hn;
                hn.x = (vkeep[0] - muv) * rstdv * sm[OFF_B + 40 + colw + 0] + sm[OFF_B + 48 + colw + 0];
                hn.y = (vkeep[1] - muv) * rstdv * sm[OFF_B + 40 + colw + 1] + sm[OFF_B + 48 + colw + 1];
                hn.z = (vkeep[2] - muv) * rstdv * sm[OFF_B + 40 + colw + 2] + sm[OFF_B + 48 + colw + 2];
                hn.w = (vkeep[3] - muv) * rstdv * sm[OFF_B + 40 + colw + 3] + sm[OFF_B + 48 + colw + 3];
                *reinterpret_cast<float4*>(
                    out + ((size_t)gR * Tt + (t - 1)) * Hh + cbase + colw) = hn;
                hprev[0] = hn.x; hprev[1] = hn.y; hprev[2] = hn.z; hprev[3] = hn.w;
            }
            if (ch == 0) sm[OFF_RSTD + r] = rstdv;   // 0 at t=0
        }
        unsigned long long ag[4][2] = {}, ac[4][2] = {};
        cp_wait<1>(); __syncthreads();                      // x ready (bufA)
        dotAx(reinterpret_cast<const ulonglong2*>(bufA) + r * 64, sw, kp,
              WMXg, WMXc, ag, ac);
        __syncthreads();
        stage32(bufA, vbase + 1024, Hh * 4, rs0, kk);       // v1 -> A
        unsigned long long rstd2;
        {
            float rv = sm[OFF_RSTD + r];
            asm("mov.b64 %0, {%1, %1};" : "=l"(rstd2) : "f"(rv));
        }
        cp_wait<1>(); __syncthreads();                      // v0 ready
        dotAv(reinterpret_cast<const ulonglong2*>(bufB) + r * 64, sw, kp, 0,
              rstd2, WMVg, WMVc, ag, ac);
        cp_wait<0>(); __syncthreads();                      // v1 ready
        dotAv(reinterpret_cast<const ulonglong2*>(bufA) + r * 64, sw, kp, 64,
              rstd2, WMVg, WMVc, ag, ac);
        red4[tid * 2 + 0] = make_float4(hsum(ag[0][0]) + hsum(ag[0][1]),
                                        hsum(ag[1][0]) + hsum(ag[1][1]),
                                        hsum(ag[2][0]) + hsum(ag[2][1]),
                                        hsum(ag[3][0]) + hsum(ag[3][1]));
        red4[tid * 2 + 1] = make_float4(hsum(ac[0][0]) + hsum(ac[0][1]),
                                        hsum(ac[1][0]) + hsum(ac[1][1]),
                                        hsum(ac[2][0]) + hsum(ac[2][1]),
                                        hsum(ac[3][0]) + hsum(ac[3][1]));
        __syncthreads();
        if (owner) {
            float G[4] = {0, 0, 0, 0}, C[4] = {0, 0, 0, 0};
#pragma unroll
            for (int kpp = 0; kpp < 8; ++kpp) {
                float4 pg = red4[(kpp * 64 + ch * 32 + r) * 2 + 0];
                float4 pc = red4[(kpp * 64 + ch * 32 + r) * 2 + 1];
                G[0] += pg.x; G[1] += pg.y; G[2] += pg.z; G[3] += pg.w;
                C[0] += pc.x; C[1] += pc.y; C[2] += pc.z; C[3] += pc.w;
            }
            float mr = muv * rstdv;
            float4 zf, cf;
            float* zp = &zf.x;
            float* cpp = &cf.x;
#pragma unroll
            for (int cc = 0; cc < 4; ++cc) {
                float gv = G[cc] + sm[OFF_B + colw + cc];
                float cv = C[cc] + sm[OFF_B + 8 + colw + cc];
                if (t > 0) {
                    gv += sm[OFF_B + 56 + colw + cc]     - mr * sm[OFF_B + 72 + colw + cc];
                    cv += sm[OFF_B + 56 + 8 + colw + cc] - mr * sm[OFF_B + 72 + 8 + colw + cc];
                }
                float sg = 1.f / (1.f + expf(-gv));
                cpp[cc] = cv;
                zp[cc]  = sg * tanhf(cv);
            }
            *reinterpret_cast<float4*>(&g_z[gR * Hh + cbase + colw])    = zf;
            *reinterpret_cast<float4*>(&g_core[gR * Hh + cbase + colw]) = cf;
        }
        bar_t += 8; grid_bar(bar_t);
        if (bid == 0 && tid >= 64 && tid < 192) {   // zero LN accs parity par^1
            int i = tid - 64;
            if (i < 64) g_rs[(par ^ 1) * 64 + i] = 0.f;
            else        g_rq[(par ^ 1) * 64 + (i - 64)] = 0.f;
        }

        // ===== PHASE B: tau = softplus(core@Wt+bt); PHASE C: a1 ============
        stage32(bufA, corebase,        Hh * 4, rs0, kk);
        stage32(bufB, corebase + 1024, Hh * 4, rs0, kk);
        unsigned long long at[4][2] = {};
        cp_wait<1>(); __syncthreads();                      // core0 ready
        dot4(reinterpret_cast<const ulonglong2*>(bufA) + r * 64, sw, kp, 0,
             WTu, at);
        __syncthreads();
        stage32(bufA, zbase, Hh * 4, rs0, kk);              // z0 -> A
        cp_wait<1>(); __syncthreads();                      // core1 ready
        dot4(reinterpret_cast<const ulonglong2*>(bufB) + r * 64, sw, kp, 64,
             WTu, at);
        red4[tid] = make_float4(hsum(at[0][0]) + hsum(at[0][1]),
                                hsum(at[1][0]) + hsum(at[1][1]),
                                hsum(at[2][0]) + hsum(at[2][1]),
                                hsum(at[3][0]) + hsum(at[3][1]));
        __syncthreads();
        stage32(bufB, zbase + 1024, Hh * 4, rs0, kk);       // z1 -> B
        if (owner) {
            float Tq[4] = {0, 0, 0, 0};
#pragma unroll
            for (int kpp = 0; kpp < 8; ++kpp) {
                float4 p = red4[kpp * 64 + ch * 32 + r];
                Tq[0] += p.x; Tq[1] += p.y; Tq[2] += p.z; Tq[3] += p.w;
            }
#pragma unroll
            for (int cc = 0; cc < 4; ++cc) {
                float tl = Tq[cc] + sm[OFF_B + 16 + colw + cc];
                float spv = (tl > 20.f) ? tl : log1pf(expf(tl));
                dtT[cc] = DTc / (spv + 1e-6f);
            }
        }
        unsigned long long af[4][2] = {};
        cp_wait<1>(); __syncthreads();                      // z0 ready
        dot4(reinterpret_cast<const ulonglong2*>(bufA) + r * 64, sw, kp, 0,
             WF1u, af);
        cp_wait<0>(); __syncthreads();                      // z1 ready
        dot4(reinterpret_cast<const ulonglong2*>(bufB) + r * 64, sw, kp, 64,
             WF1u, af);
        red4[tid] = make_float4(hsum(af[0][0]) + hsum(af[0][1]),
                                hsum(af[1][0]) + hsum(af[1][1]),
                                hsum(af[2][0]) + hsum(af[2][1]),
                                hsum(af[3][0]) + hsum(af[3][1]));
        __syncthreads();
        if (owner) {
            float F[4] = {0, 0, 0, 0};
#pragma unroll
            for (int kpp = 0; kpp < 8; ++kpp) {
                float4 p = red4[kpp * 64 + ch * 32 + r];
                F[0] += p.x; F[1] += p.y; F[2] += p.z; F[3] += p.w;
            }
            float4 a1v;
            float* ap = &a1v.x;
#pragma unroll
            for (int cc = 0; cc < 4; ++cc) {
                float f1 = F[cc] + sm[OFF_B + 24 + colw + cc];
                ap[cc] = f1 / (1.f + expf(-f1));
            }
            *reinterpret_cast<float4*>(&g_a1[gR * Hh + cbase + colw]) = a1v;
        }
        bar_t += 8; grid_bar(bar_t);

        // ===== PHASE D: f = a1@Wf2 + bf2; v = h + dt/tau * f ===============
        stage32(bufA, abase,        Hh * 4, rs0, kk);
        stage32(bufB, abase + 1024, Hh * 4, rs0, kk);
        unsigned long long ao[4][2] = {};
        cp_wait<1>(); __syncthreads();                      // a1_0 ready
        dot4(reinterpret_cast<const ulonglong2*>(bufA) + r * 64, sw, kp, 0,
             WF2u, ao);
        __syncthreads();
        if (t + 1 < Tt) {                                   // x(t+1) -> A
            stage32(bufA, xbase + (size_t)(t + 1) * DIN * 4,
                    (size_t)Tt * DIN * 4, rs0, kk);
            cp_wait<1>();
        } else {
            cp_wait<0>();
        }
        __syncthreads();                                    // a1_1 ready
        dot4(reinterpret_cast<const ulonglong2*>(bufB) + r * 64, sw, kp, 64,
             WF2u, ao);
        red4[tid] = make_float4(hsum(ao[0][0]) + hsum(ao[0][1]),
                                hsum(ao[1][0]) + hsum(ao[1][1]),
                                hsum(ao[2][0]) + hsum(ao[2][1]),
                                hsum(ao[3][0]) + hsum(ao[3][1]));
        __syncthreads();
        if (owner) {
            float F[4] = {0, 0, 0, 0};
#pragma unroll
            for (int kpp = 0; kpp < 8; ++kpp) {
                float4 p = red4[kpp * 64 + ch * 32 + r];
                F[0] += p.x; F[1] += p.y; F[2] += p.z; F[3] += p.w;
            }
            float ssum = 0.f, qsum = 0.f;
            float4 vv;
            float* vp = &vv.x;
#pragma unroll
            for (int cc = 0; cc < 4; ++cc) {
                float f = F[cc] + sm[OFF_B + 32 + colw + cc];
                float v = hprev[cc] + dtT[cc] * f;
                vkeep[cc] = v;
                vp[cc] = v;
                ssum += v; qsum += v * v;
            }
            *reinterpret_cast<float4*>(&g_v[gR * Hh + cbase + colw]) = vv;
            sm[OFF_LNR + (ch * 32 + r) * 2 + 0] = ssum;
            sm[OFF_LNR + (ch * 32 + r) * 2 + 1] = qsum;
        }
        __syncthreads();
        if (tid < 32) {    // combine ch halves: ONE atomic pair per (CTA,row)
            float s0 = sm[OFF_LNR + tid * 2 + 0] + sm[OFF_LNR + (32 + tid) * 2 + 0];
            float q0 = sm[OFF_LNR + tid * 2 + 1] + sm[OFF_LNR + (32 + tid) * 2 + 1];
            int row = rh * 32 + tid;
            atomicAdd(&g_rs[par * 64 + row], s0);
            atomicAdd(&g_rq[par * 64 + row], q0);
        }
        bar_t += 8; grid_bar(bar_t);
    }

    // final output row (t = Tt-1)
    if (owner) {
        int pp = (Tt - 1) & 1;
        float s = __ldcg(&g_rs[pp * 64 + gR]);
        float q = __ldcg(&g_rq[pp * 64 + gR]);
        float muv = s * (1.f / 512.f);
        float var = q * (1.f / 512.f) - muv * muv;
        float rstdv = rsqrtf(var + EPSc);
        float4 hn;
        hn.x = (vkeep[0] - muv) * rstdv * sm[OFF_B + 40 + colw + 0] + sm[OFF_B + 48 + colw + 0];
        hn.y = (vkeep[1] - muv) * rstdv * sm[OFF_B + 40 + colw + 1] + sm[OFF_B + 48 + colw + 1];
        hn.z = (vkeep[2] - muv) * rstdv * sm[OFF_B + 40 + colw + 2] + sm[OFF_B + 48 + colw + 2];
        hn.w = (vkeep[3] - muv) * rstdv * sm[OFF_B + 40 + colw + 3] + sm[OFF_B + 48 + colw + 3];
        *reinterpret_cast<float4*>(
            out + ((size_t)gR * Tt + (Tt - 1)) * Hh + cbase + colw) = hn;
    }
}

extern "C" void kernel_launch(void* const* d_in, const int* in_sizes, int n_in,
                              void* d_out, int out_size) {
    const float* x     = (const float*)d_in[0];
    const float* Wm    = (const float*)d_in[1];
    const float* bm    = (const float*)d_in[2];
    const float* Wf1   = (const float*)d_in[3];
    const float* bf1   = (const float*)d_in[4];
    const float* Wf2   = (const float*)d_in[5];
    const float* bf2   = (const float*)d_in[6];
    const float* Wt    = (const float*)d_in[7];
    const float* bt    = (const float*)d_in[8];
    const float* gamma = (const float*)d_in[9];
    const float* beta  = (const float*)d_in[10];
    float* out = (float*)d_out;

    cudaFuncSetAttribute(ctlnn_main, cudaFuncAttributeMaxDynamicSharedMemorySize,
                         SMEM_FLOATS * sizeof(float));

    ctlnn_reset<<<64, 256>>>();
    ctlnn_main<<<NCTA, NTHR, SMEM_FLOATS * sizeof(float)>>>(
        x, Wm, bm, Wf1, bf1, Wf2, bf2, Wt, bt, gamma, beta, out);
}

// round 10
// speedup vs baseline: 1.0489x; 1.0489x over previous
#include <cuda_runtime.h>
#include <cmath>

// ---------------------------------------------------------------------------
// CTLNN persistent kernel, round 10.
// 128 CTAs = 2 row-halves x 64 col-groups; 32 rows x 8 cols per CTA; threads
// (r:32, ch:2, kp:8), 4 cols per thread over a K/8 slice.
// NEW vs R9:
//  - tau folded through the input mapper: tauL = x@WfX + (rstd v)@WfV + const.
//    Phase B is GONE (no core exchange). Phase A emits 12 columns
//    (4 g, 4 core, 4 tauL) with single-u64 FFMA2 accumulators.
//  - split D-barrier: arrive at end of D; next phase A computes the x-dot
//    (locally staged) before waiting, hiding barrier latency.
// LayerNorm folded into phase A; cp.async double-buffered staging; FFMA2.
// ---------------------------------------------------------------------------

namespace {
constexpr int Tt   = 1024;
constexpr int DIN  = 256;
constexpr int Hh   = 512;
constexpr int NCTA = 128;
constexpr int NTHR = 512;
constexpr int NBAR = 16;
constexpr int BARSTRIDE = 32;
constexpr float DTc  = 0.01f;
constexpr float EPSc = 1e-5f;

// SMEM float offsets
constexpr int OFF_WMX   = 0;         // 16 x 256 (x-rows of Wm) [c16][k]
constexpr int OFF_WMV   = 4096;      // 16 x 512 (h-rows, gamma-folded)
constexpr int OFF_WFX   = 12288;     // 8 x 256 tau x-fold [c][k]
constexpr int OFF_WFV   = 14336;     // 8 x 512 tau v-fold (gamma-folded)
constexpr int OFF_WF1   = 18432;     // 8 x 512
constexpr int OFF_WF2   = 22528;     // 8 x 512
constexpr int OFF_STAGE = 26624;     // 2 x 2048 float4 = 16384 floats
constexpr int OFF_RED   = 43008;     // 512 x 12 floats
constexpr int OFF_LNR   = 49152;     // 128
constexpr int OFF_B     = 49280;     // 104 consts
constexpr int OFF_RSTD  = 49384;     // 32
constexpr int SMEM_FLOATS = 49424;   // ~197.7 KB
// OFF_B: 0 bmg[8] 8 bmc[8] 16 tauC0[8] 24 bf1[8] 32 bf2[8] 40 gam[8] 48 bet[8]
//        56 Bsum[16] 72 Gsum[16] 88 BsumT[8] 96 GsumT[8]
}

// Cross-CTA state
__device__ unsigned g_barArr[NBAR * BARSTRIDE];
__device__ float g_rs[128], g_rq[128];
__device__ float g_v[64 * Hh];
__device__ float g_z[64 * Hh];
__device__ float g_a1[64 * Hh];

__global__ void ctlnn_reset() {
    int i = blockIdx.x * blockDim.x + threadIdx.x;
    if (i < NBAR * BARSTRIDE) g_barArr[i] = 0u;
    if (i < 128) { g_rs[i] = 0.f; g_rq[i] = 0.f; }
    for (int k = i; k < 64 * Hh; k += gridDim.x * blockDim.x) g_v[k] = 0.f;
}

// ---- helpers --------------------------------------------------------------
__device__ __forceinline__ void cp16(float4* dst, const void* src) {
    unsigned s = (unsigned)__cvta_generic_to_shared(dst);
    asm volatile("cp.async.cg.shared.global [%0], [%1], 16;" :: "r"(s), "l"(src));
}
__device__ __forceinline__ void cp_commit() {
    asm volatile("cp.async.commit_group;" ::: "memory");
}
template <int N>
__device__ __forceinline__ void cp_wait() {
    asm volatile("cp.async.wait_group %0;" :: "n"(N) : "memory");
}
__device__ __forceinline__ void fma2(unsigned long long& d,
                                     unsigned long long a, unsigned long long b) {
    asm volatile("fma.rn.f32x2 %0, %1, %2, %3;" : "=l"(d) : "l"(a), "l"(b), "l"(d));
}
__device__ __forceinline__ unsigned long long mul2(unsigned long long a,
                                                   unsigned long long b) {
    unsigned long long d;
    asm("mul.rn.f32x2 %0, %1, %2;" : "=l"(d) : "l"(a), "l"(b));
    return d;
}
__device__ __forceinline__ float hsum(unsigned long long u) {
    float lo, hi;
    asm("mov.b64 {%0,%1}, %2;" : "=f"(lo), "=f"(hi) : "l"(u));
    return lo + hi;
}

// Distributed barrier: arrive on counter (bid % 16); threads 0..15 poll.
__device__ __forceinline__ void bar_arrive() {
    __threadfence();
    __syncthreads();
    if (threadIdx.x == 0)
        atomicAdd(&g_barArr[(blockIdx.x & (NBAR - 1)) * BARSTRIDE], 1u);
}
__device__ __forceinline__ void bar_wait(unsigned target8) {
    if (threadIdx.x < NBAR) {
        unsigned v;
        do {
            asm volatile("ld.global.acquire.gpu.u32 %0, [%1];"
                         : "=r"(v) : "l"(&g_barArr[threadIdx.x * BARSTRIDE]));
        } while (v < target8);
    }
    __syncthreads();
}
__device__ __forceinline__ void grid_bar(unsigned target8) {
    bar_arrive();
    bar_wait(target8);
}

// Stage one 32-row x 64-granule(16B) chunk into SMEM with XOR swizzle.
__device__ __forceinline__ void stage32(float4* __restrict__ dst,
                                        const char* __restrict__ gbase,
                                        size_t rstrideB, int rs0, int kk) {
#pragma unroll
    for (int i = 0; i < 4; ++i) {
        int rs = rs0 + i * 8;
        cp16(dst + rs * 64 + (kk ^ (rs & 7)),
             gbase + (size_t)rs * rstrideB + kk * 16);
    }
    cp_commit();
}

// 12-output chunk dot: 4 gate + 4 core + 4 tau columns. ws = weight granule
// stride per column (64 for x-side, 128 for v-side).
template <bool SCALE>
__device__ __forceinline__ void dot12(const ulonglong2* __restrict__ sp, int sw,
                                      int kp, int goff,
                                      const ulonglong2* __restrict__ wg,
                                      const ulonglong2* __restrict__ wc,
                                      const ulonglong2* __restrict__ wt,
                                      int ws, unsigned long long sc,
                                      unsigned long long acc[12]) {
#pragma unroll
    for (int j = 0; j < 8; ++j) {
        int l = j * 8 + kp;
        ulonglong2 a = sp[l ^ sw];
        if (SCALE) { a.x = mul2(a.x, sc); a.y = mul2(a.y, sc); }
        int wi = goff + l;
#pragma unroll
        for (int cc = 0; cc < 4; ++cc) {
            ulonglong2 g = wg[cc * ws + wi];
            fma2(acc[cc], a.x, g.x); fma2(acc[cc], a.y, g.y);
            ulonglong2 c = wc[cc * ws + wi];
            fma2(acc[4 + cc], a.x, c.x); fma2(acc[4 + cc], a.y, c.y);
            ulonglong2 t2 = wt[cc * ws + wi];
            fma2(acc[8 + cc], a.x, t2.x); fma2(acc[8 + cc], a.y, t2.y);
        }
    }
}

// Generic 4-col dot (phases C/D), weight col stride 128 granules.
__device__ __forceinline__ void dot4(const ulonglong2* __restrict__ sp, int sw,
                                     int kp, int goff,
                                     const ulonglong2* __restrict__ w,
                                     unsigned long long acc[4][2]) {
#pragma unroll
    for (int j = 0; j < 8; ++j) {
        int l = j * 8 + kp;
        ulonglong2 a = sp[l ^ sw];
        int wi = goff + l;
#pragma unroll
        for (int cc = 0; cc < 4; ++cc) {
            ulonglong2 ww = w[cc * 128 + wi];
            fma2(acc[cc][0], a.x, ww.x);
            fma2(acc[cc][1], a.y, ww.y);
        }
    }
}

__global__ void __launch_bounds__(NTHR, 1)
ctlnn_main(const float* __restrict__ x,
           const float* __restrict__ Wm,  const float* __restrict__ bm,
           const float* __restrict__ Wf1, const float* __restrict__ bf1,
           const float* __restrict__ Wf2, const float* __restrict__ bf2,
           const float* __restrict__ Wt,  const float* __restrict__ bt,
           const float* __restrict__ gamma, const float* __restrict__ beta,
           float* __restrict__ out) {
    extern __shared__ __align__(16) float sm[];
    const int tid = threadIdx.x;
    const int bid = blockIdx.x;
    const int rh  = bid >> 6;
    const int cg  = bid & 63;
    const int cbase = cg * 8;

    // ---- one-time weight slice load ----
    for (int idx = tid; idx < 16 * 256; idx += NTHR) {   // Wm x-rows
        int c = idx >> 8, k = idx & 255;
        int srccol = (c < 8) ? (cbase + c) : (512 + cbase + (c - 8));
        sm[OFF_WMX + idx] = Wm[k * 1024 + srccol];
    }
    for (int idx = tid; idx < 16 * 512; idx += NTHR) {   // Wm h-rows * gamma
        int c = idx >> 9, k = idx & 511;
        int srccol = (c < 8) ? (cbase + c) : (512 + cbase + (c - 8));
        sm[OFF_WMV + idx] = Wm[(256 + k) * 1024 + srccol] * gamma[k];
    }
    for (int idx = tid; idx < 8 * 512; idx += NTHR) {
        int c = idx >> 9, k = idx & 511;
        int col = cbase + c;
        sm[OFF_WF1 + idx] = Wf1[k * 512 + col];
        sm[OFF_WF2 + idx] = Wf2[k * 512 + col];
    }
    if (tid < 8) {
        int col = cbase + tid;
        sm[OFF_B +  0 + tid] = bm[col];
        sm[OFF_B +  8 + tid] = bm[512 + col];
        sm[OFF_B + 24 + tid] = bf1[col];
        sm[OFF_B + 32 + tid] = bf2[col];
        sm[OFF_B + 40 + tid] = gamma[col];
        sm[OFF_B + 48 + tid] = beta[col];
    }
    {   // per-column LN-fold constants Bsum/Gsum for g/core (16 A-cols)
        int w = tid >> 5, lane = tid & 31;
        if (w < 16) {
            int srccol = (w < 8) ? (cbase + w) : (512 + cbase + (w - 8));
            float sb = 0.f, sg = 0.f;
            for (int k = lane; k < 512; k += 32) {
                float wv = Wm[(256 + k) * 1024 + srccol];
                sb += beta[k] * wv;
                sg += gamma[k] * wv;
            }
#pragma unroll
            for (int o = 16; o; o >>= 1) {
                sb += __shfl_xor_sync(~0u, sb, o);
                sg += __shfl_xor_sync(~0u, sg, o);
            }
            if (lane == 0) { sm[OFF_B + 56 + w] = sb; sm[OFF_B + 72 + w] = sg; }
        }
    }
    // ---- tau fold: WfX = WmX_core@Wt, WfV = WmV_core@Wt (then gamma-fold) --
    {
        float* WtS = sm + OFF_STAGE;           // 8 x 512 [c][j]
        float* Tm  = sm + OFF_STAGE + 4096;    // 24 x 512 tile
        for (int idx = tid; idx < 8 * 512; idx += NTHR) {
            int c = idx >> 9, j = idx & 511;
            WtS[idx] = Wt[j * 512 + cbase + c];
        }
        __syncthreads();
        for (int tile = 0; tile < 32; ++tile) {
            int k0 = tile * 24;
            for (int idx = tid; idx < 24 * 128; idx += NTHR) {
                int row = idx >> 7, jj = idx & 127;
                reinterpret_cast<float4*>(Tm)[row * 128 + jj] =
                    __ldg(reinterpret_cast<const float4*>(
                        Wm + (size_t)(k0 + row) * 1024 + 512) + jj);
            }
            __syncthreads();
            int row = tid >> 3, c = tid & 7;
            if (row < 24) {
                const float4* tm = reinterpret_cast<const float4*>(Tm) + row * 128;
                const float4* wt4 = reinterpret_cast<const float4*>(WtS) + c * 128;
                float s = 0.f;
                for (int jj = 0; jj < 128; ++jj) {
                    float4 a = tm[jj], b = wt4[jj];
                    s += a.x * b.x + a.y * b.y + a.z * b.z + a.w * b.w;
                }
                int k = k0 + row;
                if (k < 256) sm[OFF_WFX + c * 256 + k] = s;
                else         sm[OFF_WFV + c * 512 + (k - 256)] = s;   // raw
            }
            __syncthreads();
        }
        // BsumT/GsumT (raw WFV) and tau const C0
        int w = tid >> 5, lane = tid & 31;
        if (w < 8) {                       // BsumT/GsumT for c=w
            float sb = 0.f, sg = 0.f;
            for (int k = lane; k < 512; k += 32) {
                float raw = sm[OFF_WFV + w * 512 + k];
                sb += beta[k] * raw;
                sg += gamma[k] * raw;
            }
#pragma unroll
            for (int o = 16; o; o >>= 1) {
                sb += __shfl_xor_sync(~0u, sb, o);
                sg += __shfl_xor_sync(~0u, sg, o);
            }
            if (lane == 0) { sm[OFF_B + 88 + w] = sb; sm[OFF_B + 96 + w] = sg; }
        } else if (w < 16) {               // C0 for c=w-8
            int c = w - 8;
            float s = 0.f;
            for (int j = lane; j < 512; j += 32)
                s += bm[512 + j] * WtS[c * 512 + j];
#pragma unroll
            for (int o = 16; o; o >>= 1)
                s += __shfl_xor_sync(~0u, s, o);
            if (lane == 0) sm[OFF_B + 16 + c] = s + bt[cbase + c];
        }
        __syncthreads();
        for (int idx = tid; idx < 8 * 512; idx += NTHR)   // gamma-fold WFV
            sm[OFF_WFV + idx] *= gamma[idx & 511];
        __syncthreads();
    }

    float4* bufA = reinterpret_cast<float4*>(sm + OFF_STAGE);
    float4* bufB = bufA + 32 * 64;
    float4* red4 = reinterpret_cast<float4*>(sm + OFF_RED);

    const int r   = tid & 31;
    const int ch  = (tid >> 5) & 1;
    const int kp  = tid >> 6;
    const int sw  = r & 7;
    const int rs0 = tid >> 6;
    const int kk  = tid & 63;
    const int gR  = rh * 32 + r;
    const int colw = ch * 4;
    const bool owner = (kp == 0);

    const ulonglong2* WMXg = reinterpret_cast<const ulonglong2*>(sm + OFF_WMX) + colw * 64;
    const ulonglong2* WMXc = reinterpret_cast<const ulonglong2*>(sm + OFF_WMX) + (8 + colw) * 64;
    const ulonglong2* WFXu = reinterpret_cast<const ulonglong2*>(sm + OFF_WFX) + colw * 64;
    const ulonglong2* WMVg = reinterpret_cast<const ulonglong2*>(sm + OFF_WMV) + colw * 128;
    const ulonglong2* WMVc = reinterpret_cast<const ulonglong2*>(sm + OFF_WMV) + (8 + colw) * 128;
    const ulonglong2* WFVu = reinterpret_cast<const ulonglong2*>(sm + OFF_WFV) + colw * 128;
    const ulonglong2* WF1u = reinterpret_cast<const ulonglong2*>(sm + OFF_WF1) + colw * 128;
    const ulonglong2* WF2u = reinterpret_cast<const ulonglong2*>(sm + OFF_WF2) + colw * 128;

    const char* xbase = (const char*)(x + (size_t)rh * 32 * Tt * DIN);
    const char* vbase = (const char*)(g_v  + (size_t)rh * 32 * Hh);
    const char* zbase = (const char*)(g_z  + (size_t)rh * 32 * Hh);
    const char* abase = (const char*)(g_a1 + (size_t)rh * 32 * Hh);

    float hprev[4] = {0.f, 0.f, 0.f, 0.f};
    float dtT[4]   = {0.f, 0.f, 0.f, 0.f};
    float vkeep[4] = {0.f, 0.f, 0.f, 0.f};
    unsigned bar_t = 0;

    // prefetch x(t=0) into bufA
    stage32(bufA, xbase, (size_t)Tt * DIN * 4, rs0, kk);

    for (int t = 0; t < Tt; ++t) {
        const int par = t & 1;

        // ================= PHASE A (12 outputs; LN + tau folded) ===========
        unsigned long long acc[12] = {};
        cp_wait<0>(); __syncthreads();                     // x(t) ready (bufA)
        dot12<false>(reinterpret_cast<const ulonglong2*>(bufA) + r * 64, sw,
                     kp, 0, WMXg, WMXc, WFXu, 64, 0ull, acc);
        // hide the D-barrier behind the x-dot
        bar_wait(bar_t);
        stage32(bufB, vbase, Hh * 4, rs0, kk);             // v0 -> B
        stage32(bufA, vbase + 1024, Hh * 4, rs0, kk);      // v1 -> A
        float muv = 0.f, rstdv = 0.f;
        if (owner) {
            if (t > 0) {   // finalize step t-1
                int pp = (t - 1) & 1;
                float s = __ldcg(&g_rs[pp * 64 + gR]);
                float q = __ldcg(&g_rq[pp * 64 + gR]);
                muv = s * (1.f / 512.f);
                float var = q * (1.f / 512.f) - muv * muv;
                rstdv = rsqrtf(var + EPSc);
                float4 hn;
                hn.x = (vkeep[0] - muv) * rstdv * sm[OFF_B + 40 + colw + 0] + sm[OFF_B + 48 + colw + 0];
                hn.y = (vkeep[1] - muv) * rstdv * sm[OFF_B + 40 + colw + 1] + sm[OFF_B + 48 + colw + 1];
                hn.z = (vkeep[2] - muv) * rstdv * sm[OFF_B + 40 + colw + 2] + sm[OFF_B + 48 + colw + 2];
                hn.w = (vkeep[3] - muv) * rstdv * sm[OFF_B + 40 + colw + 3] + sm[OFF_B + 48 + colw + 3];
                *reinterpret_cast<float4*>(
                    out + ((size_t)gR * Tt + (t - 1)) * Hh + cbase + colw) = hn;
                hprev[0] = hn.x; hprev[1] = hn.y; hprev[2] = hn.z; hprev[3] = hn.w;
            }
            if (ch == 0) sm[OFF_RSTD + r] = rstdv;
        }
        cp_wait<1>(); __syncthreads();                     // v0 ready
        unsigned long long rstd2;
        {
            float rv = sm[OFF_RSTD + r];
            asm("mov.b64 %0, {%1, %1};" : "=l"(rstd2) : "f"(rv));
        }
        dot12<true>(reinterpret_cast<const ulonglong2*>(bufB) + r * 64, sw,
                    kp, 0, WMVg, WMVc, WFVu, 128, rstd2, acc);
        cp_wait<0>(); __syncthreads();                     // v1 ready
        dot12<true>(reinterpret_cast<const ulonglong2*>(bufA) + r * 64, sw,
                    kp, 64, WMVg, WMVc, WFVu, 128, rstd2, acc);
        {
            float4* rA = red4 + tid * 3;
            rA[0] = make_float4(hsum(acc[0]), hsum(acc[1]), hsum(acc[2]), hsum(acc[3]));
            rA[1] = make_float4(hsum(acc[4]), hsum(acc[5]), hsum(acc[6]), hsum(acc[7]));
            rA[2] = make_float4(hsum(acc[8]), hsum(acc[9]), hsum(acc[10]), hsum(acc[11]));
        }
        __syncthreads();
        if (owner) {
            float G[4] = {0, 0, 0, 0}, C[4] = {0, 0, 0, 0}, T[4] = {0, 0, 0, 0};
#pragma unroll
            for (int kpp = 0; kpp < 8; ++kpp) {
                const float4* p = red4 + (kpp * 64 + ch * 32 + r) * 3;
                float4 a = p[0], b = p[1], d = p[2];
                G[0] += a.x; G[1] += a.y; G[2] += a.z; G[3] += a.w;
                C[0] += b.x; C[1] += b.y; C[2] += b.z; C[3] += b.w;
                T[0] += d.x; T[1] += d.y; T[2] += d.z; T[3] += d.w;
            }
            float mr = muv * rstdv;
            float4 zf;
            float* zp = &zf.x;
#pragma unroll
            for (int cc = 0; cc < 4; ++cc) {
                float gv = G[cc] + sm[OFF_B + colw + cc];
                float cv = C[cc] + sm[OFF_B + 8 + colw + cc];
                float tl = T[cc] + sm[OFF_B + 16 + colw + cc];
                if (t > 0) {
                    gv += sm[OFF_B + 56 + colw + cc]     - mr * sm[OFF_B + 72 + colw + cc];
                    cv += sm[OFF_B + 56 + 8 + colw + cc] - mr * sm[OFF_B + 72 + 8 + colw + cc];
                    tl += sm[OFF_B + 88 + colw + cc]     - mr * sm[OFF_B + 96 + colw + cc];
                }
                float sg = 1.f / (1.f + expf(-gv));
                zp[cc] = sg * tanhf(cv);
                float spv = (tl > 20.f) ? tl : log1pf(expf(tl));
                dtT[cc] = DTc / (spv + 1e-6f);
            }
            *reinterpret_cast<float4*>(&g_z[gR * Hh + cbase + colw]) = zf;
        }
        bar_t += 8; grid_bar(bar_t);
        if (bid == 0 && tid >= 64 && tid < 192) {   // zero LN accs parity par^1
            int i = tid - 64;
            if (i < 64) g_rs[(par ^ 1) * 64 + i] = 0.f;
            else        g_rq[(par ^ 1) * 64 + (i - 64)] = 0.f;
        }

        // ================= PHASE C: a1 = silu(z@Wf1 + bf1) =================
        stage32(bufA, zbase,        Hh * 4, rs0, kk);
        stage32(bufB, zbase + 1024, Hh * 4, rs0, kk);
        unsigned long long af[4][2] = {};
        cp_wait<1>(); __syncthreads();                     // z0 ready
        dot4(reinterpret_cast<const ulonglong2*>(bufA) + r * 64, sw, kp, 0,
             WF1u, af);
        cp_wait<0>(); __syncthreads();                     // z1 ready
        dot4(reinterpret_cast<const ulonglong2*>(bufB) + r * 64, sw, kp, 64,
             WF1u, af);
        red4[tid] = make_float4(hsum(af[0][0]) + hsum(af[0][1]),
                                hsum(af[1][0]) + hsum(af[1][1]),
                                hsum(af[2][0]) + hsum(af[2][1]),
                                hsum(af[3][0]) + hsum(af[3][1]));
        __syncthreads();
        if (owner) {
            float F[4] = {0, 0, 0, 0};
#pragma unroll
            for (int kpp = 0; kpp < 8; ++kpp) {
                float4 p = red4[kpp * 64 + ch * 32 + r];
                F[0] += p.x; F[1] += p.y; F[2] += p.z; F[3] += p.w;
            }
            float4 a1v;
            float* ap = &a1v.x;
#pragma unroll
            for (int cc = 0; cc < 4; ++cc) {
                float f1 = F[cc] + sm[OFF_B + 24 + colw + cc];
                ap[cc] = f1 / (1.f + expf(-f1));
            }
            *reinterpret_cast<float4*>(&g_a1[gR * Hh + cbase + colw]) = a1v;
        }
        bar_t += 8; grid_bar(bar_t);

        // ===== PHASE D: f = a1@Wf2 + bf2; v = h + dt/tau * f ===============
        stage32(bufA, abase,        Hh * 4, rs0, kk);
        stage32(bufB, abase + 1024, Hh * 4, rs0, kk);
        unsigned long long ao[4][2] = {};
        cp_wait<1>(); __syncthreads();                     // a1_0 ready
        dot4(reinterpret_cast<const ulonglong2*>(bufA) + r * 64, sw, kp, 0,
             WF2u, ao);
        __syncthreads();
        if (t + 1 < Tt) {                                  // x(t+1) -> A
            stage32(bufA, xbase + (size_t)(t + 1) * DIN * 4,
                    (size_t)Tt * DIN * 4, rs0, kk);
            cp_wait<1>();
        } else {
            cp_wait<0>();
        }
        __syncthreads();                                   // a1_1 ready
        dot4(reinterpret_cast<const ulonglong2*>(bufB) + r * 64, sw, kp, 64,
             WF2u, ao);
        red4[tid] = make_float4(hsum(ao[0][0]) + hsum(ao[0][1]),
                                hsum(ao[1][0]) + hsum(ao[1][1]),
                                hsum(ao[2][0]) + hsum(ao[2][1]),
                                hsum(ao[3][0]) + hsum(ao[3][1]));
        __syncthreads();
        if (owner) {
            float F[4] = {0, 0, 0, 0};
#pragma unroll
            for (int kpp = 0; kpp < 8; ++kpp) {
                float4 p = red4[kpp * 64 + ch * 32 + r];
                F[0] += p.x; F[1] += p.y; F[2] += p.z; F[3] += p.w;
            }
            float ssum = 0.f, qsum = 0.f;
            float4 vv;
            float* vp = &vv.x;
#pragma unroll
            for (int cc = 0; cc < 4; ++cc) {
                float f = F[cc] + sm[OFF_B + 32 + colw + cc];
                float v = hprev[cc] + dtT[cc] * f;
                vkeep[cc] = v;
                vp[cc] = v;
                ssum += v; qsum += v * v;
            }
            *reinterpret_cast<float4*>(&g_v[gR * Hh + cbase + colw]) = vv;
            sm[OFF_LNR + (ch * 32 + r) * 2 + 0] = ssum;
            sm[OFF_LNR + (ch * 32 + r) * 2 + 1] = qsum;
        }
        __syncthreads();
        if (tid < 32) {    // combine ch halves: ONE atomic pair per (CTA,row)
            float s0 = sm[OFF_LNR + tid * 2 + 0] + sm[OFF_LNR + (32 + tid) * 2 + 0];
            float q0 = sm[OFF_LNR + tid * 2 + 1] + sm[OFF_LNR + (32 + tid) * 2 + 1];
            int row = rh * 32 + tid;
            atomicAdd(&g_rs[par * 64 + row], s0);
            atomicAdd(&g_rq[par * 64 + row], q0);
        }
        bar_arrive();           // split: wait happens in next phase A
        bar_t += 8;
    }

    bar_wait(bar_t);
    // final output row (t = Tt-1)
    if (owner) {
        int pp = (Tt - 1) & 1;
        float s = __ldcg(&g_rs[pp * 64 + gR]);
        float q = __ldcg(&g_rq[pp * 64 + gR]);
        float muv = s * (1.f / 512.f);
        float var = q * (1.f / 512.f) - muv * muv;
        float rstdv = rsqrtf(var + EPSc);
        float4 hn;
        hn.x = (vkeep[0] - muv) * rstdv * sm[OFF_B + 40 + colw + 0] + sm[OFF_B + 48 + colw + 0];
        hn.y = (vkeep[1] - muv) * rstdv * sm[OFF_B + 40 + colw + 1] + sm[OFF_B + 48 + colw + 1];
        hn.z = (vkeep[2] - muv) * rstdv * sm[OFF_B + 40 + colw + 2] + sm[OFF_B + 48 + colw + 2];
        hn.w = (vkeep[3] - muv) * rstdv * sm[OFF_B + 40 + colw + 3] + sm[OFF_B + 48 + colw + 3];
        *reinterpret_cast<float4*>(
            out + ((size_t)gR * Tt + (Tt - 1)) * Hh + cbase + colw) = hn;
    }
}

extern "C" void kernel_launch(void* const* d_in, const int* in_sizes, int n_in,
                              void* d_out, int out_size) {
    const float* x     = (const float*)d_in[0];
    const float* Wm    = (const float*)d_in[1];
    const float* bm    = (const float*)d_in[2];
    const float* Wf1   = (const float*)d_in[3];
    const float* bf1   = (const float*)d_in[4];
    const float* Wf2   = (const float*)d_in[5];
    const float* bf2   = (const float*)d_in[6];
    const float* Wt    = (const float*)d_in[7];
    const float* bt    = (const float*)d_in[8];
    const float* gamma = (const float*)d_in[9];
    const float* beta  = (const float*)d_in[10];
    float* out = (float*)d_out;

    cudaFuncSetAttribute(ctlnn_main, cudaFuncAttributeMaxDynamicSharedMemorySize,
                         SMEM_FLOATS * sizeof(float));

    ctlnn_reset<<<64, 256>>>();
    ctlnn_main<<<NCTA, NTHR, SMEM_FLOATS * sizeof(float)>>>(
        x, Wm, bm, Wf1, bf1, Wf2, bf2, Wt, bt, gamma, beta, out);
}